// round 15
// baseline (speedup 1.0000x reference)
#include <cuda_runtime.h>
#include <cuda_fp16.h>
#include <math.h>
#include <stdint.h>

#define D_MODEL 512
#define HEADS   8
#define DKH     64
#define SEQ     2048
#define BATCH   4
#define D_FF    1024
#define NROWS   (BATCH*SEQ)   // 8192

// Scratch (static device arrays — no allocation at runtime)
__device__ float    g_x  [NROWS * D_MODEL];          // residual stream (fp32)
__device__ uint32_t g_xnh[NROWS * D_MODEL / 2];      // LN output, fp16 pairs
__device__ uint32_t g_ench[NROWS * D_MODEL / 2];     // encoder_output fp16
__device__ uint32_t g_hh [NROWS * D_FF / 2];         // FFN hidden fp16
__device__ uint32_t g_w1h[D_MODEL * D_FF / 2];       // W1 fp16
__device__ uint32_t g_w2h[D_FF * D_MODEL / 2];       // W2 fp16
__device__ uint32_t g_pm [BATCH * SEQ * (SEQ / 32)]; // packed mask bits (2MB)

// ---------------------------------------------------------------------------
// helpers
// ---------------------------------------------------------------------------
__device__ __forceinline__ uint32_t f2h2(float lo, float hi) {
    __half2 h = __floats2half2_rn(lo, hi);
    return *(uint32_t*)&h;
}
__device__ __forceinline__ uint32_t h2lo(uint32_t a, uint32_t b) {  // {a.h0,b.h0}
    return __byte_perm(a, b, 0x5410);
}
__device__ __forceinline__ uint32_t h2hi(uint32_t a, uint32_t b) {  // {a.h1,b.h1}
    return __byte_perm(a, b, 0x7632);
}
__device__ __forceinline__ uint32_t hex2(uint32_t t) {   // 2^t per fp16 lane
    uint32_t r;
    asm("ex2.approx.f16x2 %0, %1;" : "=r"(r) : "r"(t));
    return r;
}

__device__ __forceinline__ void mma_f16(float c[4],
                                        uint32_t a0, uint32_t a1, uint32_t a2, uint32_t a3,
                                        uint32_t b0, uint32_t b1) {
    asm volatile(
        "mma.sync.aligned.m16n8k16.row.col.f32.f16.f16.f32 "
        "{%0,%1,%2,%3}, {%4,%5,%6,%7}, {%8,%9}, {%0,%1,%2,%3};\n"
        : "+f"(c[0]), "+f"(c[1]), "+f"(c[2]), "+f"(c[3])
        : "r"(a0), "r"(a1), "r"(a2), "r"(a3), "r"(b0), "r"(b1));
}

#define L2E 1.4426950408889634f
#define ONE2 0x3C003C00u   // fp16 {1.0, 1.0}

// ---------------------------------------------------------------------------
// fp32 -> fp16 pair converter (grid-stride, float4 -> uint2)
// ---------------------------------------------------------------------------
__global__ void cvt_h_kernel(const float* __restrict__ x,
                             uint32_t* __restrict__ yh, int n4) {
    int i = blockIdx.x * blockDim.x + threadIdx.x;
    int stride = gridDim.x * blockDim.x;
    for (; i < n4; i += stride) {
        float4 v = ((const float4*)x)[i];
        ((uint2*)yh)[i] = make_uint2(f2h2(v.x, v.y), f2h2(v.z, v.w));
    }
}

// ---------------------------------------------------------------------------
// Mask packing: bit j of pm[i/32] = (mask[i] != 0). 1 warp handles 1024 ints.
// ---------------------------------------------------------------------------
__device__ __forceinline__ uint32_t spread4(uint32_t x) {
    x &= 0xFFu;
    x = (x | (x << 12)) & 0x000F000Fu;
    x = (x | (x << 6))  & 0x03030303u;
    x = (x | (x << 3))  & 0x11111111u;
    return x;
}

__global__ void pack_mask_kernel(const int* __restrict__ mask,
                                 uint32_t* __restrict__ pm) {
    int w    = (blockIdx.x * blockDim.x + threadIdx.x) >> 5;
    int lane = threadIdx.x & 31;
    size_t base = (size_t)w * 1024;
    #pragma unroll
    for (int it = 0; it < 8; it++) {
        int4 v = *(const int4*)(mask + base + it * 128 + lane * 4);
        uint32_t b0 = __ballot_sync(0xffffffffu, v.x != 0);
        uint32_t b1 = __ballot_sync(0xffffffffu, v.y != 0);
        uint32_t b2 = __ballot_sync(0xffffffffu, v.z != 0);
        uint32_t b3 = __ballot_sync(0xffffffffu, v.w != 0);
        if (lane < 4) {
            uint32_t word =  spread4(b0 >> (8 * lane))
                          | (spread4(b1 >> (8 * lane)) << 1)
                          | (spread4(b2 >> (8 * lane)) << 2)
                          | (spread4(b3 >> (8 * lane)) << 3);
            pm[base / 32 + it * 4 + lane] = word;
        }
    }
}

// ---------------------------------------------------------------------------
// LayerNorm: one WARP per row, shuffle-only reduction, emits fp16 pairs.
// ---------------------------------------------------------------------------
__global__ __launch_bounds__(256)
void ln_kernel(const float* __restrict__ x,
               const float* __restrict__ gamma,
               const float* __restrict__ beta,
               uint32_t* __restrict__ yh) {
    const int lane = threadIdx.x & 31;
    const int row  = blockIdx.x * 8 + (threadIdx.x >> 5);
    const float4* xr = (const float4*)(x + (size_t)row * D_MODEL);

    float4 v[4];
    float s = 0.0f, ss = 0.0f;
    #pragma unroll
    for (int i = 0; i < 4; i++) {
        v[i] = xr[lane + 32 * i];
        s  += v[i].x + v[i].y + v[i].z + v[i].w;
        ss += v[i].x*v[i].x + v[i].y*v[i].y + v[i].z*v[i].z + v[i].w*v[i].w;
    }
    #pragma unroll
    for (int o = 16; o > 0; o >>= 1) {
        s  += __shfl_xor_sync(0xffffffffu, s,  o);
        ss += __shfl_xor_sync(0xffffffffu, ss, o);
    }
    float mu  = s * (1.0f / D_MODEL);
    float var = ss * (1.0f / D_MODEL) - mu * mu;
    float rs  = rsqrtf(var + 1e-5f);

    uint2* yr = (uint2*)(yh + (size_t)row * (D_MODEL / 2));
    #pragma unroll
    for (int i = 0; i < 4; i++) {
        float4 g4 = ((const float4*)gamma)[lane + 32 * i];
        float4 b4 = ((const float4*)beta)[lane + 32 * i];
        float o0 = (v[i].x - mu) * rs * g4.x + b4.x;
        float o1 = (v[i].y - mu) * rs * g4.y + b4.y;
        float o2 = (v[i].z - mu) * rs * g4.z + b4.z;
        float o3 = (v[i].w - mu) * rs * g4.w + b4.w;
        yr[lane + 32 * i] = make_uint2(f2h2(o0, o1), f2h2(o2, o3));
    }
}

// ---------------------------------------------------------------------------
// Flash attention, fp16 mma. BM=128, 256 threads, warp tile 16x64.
// Cross-tile pipelined PV with a THREE-stage K/V ring: PV(t-1) reads stage
// (t-1)%3, which is next written at t+2 — the single barrier at t+1 strictly
// separates those events (fixes the R14 2-stage use-after-write race).
// ---------------------------------------------------------------------------
#define BM    128
#define QP_S  20
#define KP_S  20
#define VP_S  68
#define KSTG  (64*KP_S + 16*VP_S)    // uint2 per K/V stage (2368)
#define ATTN_SMEM_BYTES ((128*QP_S + 3*KSTG) * 8)
#define ROWU  (D_MODEL / 2)          // u32 per row (256)

__global__ __launch_bounds__(256, 2)
void attn_mma_kernel(const uint32_t* __restrict__ Qh,
                     const uint32_t* __restrict__ KVh,
                     const uint32_t* __restrict__ pm,   // packed mask, may be null
                     const float* __restrict__ res,
                     float* __restrict__ out) {
    extern __shared__ uint2 sm2[];
    uint2* Qp     = sm2;
    uint2* KVbase = Qp + 128 * QP_S;

    const int q0   = blockIdx.x * BM;
    const int h    = blockIdx.y;
    const int b    = blockIdx.z;
    const int tid  = threadIdx.x;
    const int lane = tid & 31;
    const int warp = tid >> 5;
    const int g    = lane >> 2;
    const int tig  = lane & 3;
    const int wrow = warp * 16;

    const __half2 qscale = __float2half2_rn(0.125f);   // exact (power of 2)

    #pragma unroll
    for (int it = 0; it < 2; it++) {
        int i = tid + it * 256;
        int r = i >> 2, cc = i & 3;
        const uint32_t* src = Qh + (size_t)(b * SEQ + q0 + r) * ROWU + h * 32 + cc * 8;
        uint4 u0 = *(const uint4*)src;
        uint4 u1 = *(const uint4*)(src + 4);
        uint32_t u[8] = {u0.x, u0.y, u0.z, u0.w, u1.x, u1.y, u1.z, u1.w};
        #pragma unroll
        for (int k = 0; k < 8; k++) {
            __half2 hv = __hmul2(*(__half2*)&u[k], qscale);
            u[k] = *(uint32_t*)&hv;
        }
        uint4* d4 = (uint4*)(Qp + r * QP_S + cc * 4);
        d4[0] = make_uint4(u[0], u[4], u[1], u[5]);
        d4[1] = make_uint4(u[2], u[6], u[3], u[7]);
    }

    float oacc[8][4];
    #pragma unroll
    for (int i = 0; i < 8; i++)
        #pragma unroll
        for (int j = 0; j < 4; j++) oacc[i][j] = 0.0f;
    float sumacc[4] = {0.0f, 0.0f, 0.0f, 0.0f};

    float mrow[2] = {-INFINITY, -INFINITY};

    const int kr  = tid >> 2,  kcc = tid & 3;
    const int vcc = tid & 15;
    const int vks = (tid >> 6) & 3, vtr = (tid >> 4) & 3;
    const int vr0 = vks * 16 + 2 * vtr;

    uint4 kf[2];
    uint2 vf[4];

    auto ldg_tile = [&](int k0) {
        const uint32_t* ks_ = KVh + (size_t)(b * SEQ + k0 + kr) * ROWU + h * 32 + kcc * 8;
        kf[0] = *(const uint4*)ks_;
        kf[1] = *(const uint4*)(ks_ + 4);
        const uint32_t* vs_ = KVh + (size_t)(b * SEQ + k0 + vr0) * ROWU + h * 32 + vcc * 2;
        vf[0] = *(const uint2*)vs_;
        vf[1] = *(const uint2*)(vs_ + (size_t)1 * ROWU);
        vf[2] = *(const uint2*)(vs_ + (size_t)8 * ROWU);
        vf[3] = *(const uint2*)(vs_ + (size_t)9 * ROWU);
    };
    auto sts_tile = [&](uint2* Kp, uint2* Vp) {
        uint4* dk = (uint4*)(Kp + kr * KP_S + kcc * 4);
        dk[0] = make_uint4(kf[0].x, kf[1].x, kf[0].y, kf[1].y);
        dk[1] = make_uint4(kf[0].z, kf[1].z, kf[0].w, kf[1].w);
        uint4* dv = (uint4*)(Vp + (vks * 4 + vtr) * VP_S + vcc * 4);
        dv[0] = make_uint4(h2lo(vf[0].x, vf[1].x), h2lo(vf[2].x, vf[3].x),
                           h2hi(vf[0].x, vf[1].x), h2hi(vf[2].x, vf[3].x));
        dv[1] = make_uint4(h2lo(vf[0].y, vf[1].y), h2lo(vf[2].y, vf[3].y),
                           h2hi(vf[0].y, vf[1].y), h2hi(vf[2].y, vf[3].y));
    };

    // deferred-PV state: P fragments of previous tile + its V stage
    uint32_t pAv[4][4];
    uint2* Vprev = nullptr;

    ldg_tile(0);

    int stage = 0;                     // kt % 3
    for (int kt = 0; kt < SEQ / 64; kt++) {
        uint2* Kp = KVbase + stage * KSTG;
        uint2* Vp = Kp + 64 * KP_S;
        sts_tile(Kp, Vp);
        __syncthreads();   // stage ready; all warps done with tile kt-1 (incl. deferred PV)
        if (kt + 1 < SEQ / 64) ldg_tile((kt + 1) * 64);

        uint2 pmA, pmB;
        if (pm != nullptr) {
            const uint32_t* pr = pm + ((size_t)(b * SEQ + q0 + wrow + g)) * (SEQ / 32) + kt * 2;
            pmA = *(const uint2*)pr;
            pmB = *(const uint2*)(pr + (size_t)8 * (SEQ / 32));
        }

        // ---- S = Q K^T (tile t) ----
        float sacc[8][4];
        #pragma unroll
        for (int i = 0; i < 8; i++)
            #pragma unroll
            for (int j = 0; j < 4; j++) sacc[i][j] = 0.0f;

        #pragma unroll
        for (int ks = 0; ks < 4; ks++) {
            uint2 qa = Qp[(wrow + g)     * QP_S + ks * 4 + tig];
            uint2 qb = Qp[(wrow + 8 + g) * QP_S + ks * 4 + tig];
            #pragma unroll
            for (int nf = 0; nf < 8; nf++) {
                uint2 kb = Kp[(nf * 8 + g) * KP_S + ks * 4 + tig];
                mma_f16(sacc[nf], qa.x, qb.x, qa.y, qb.y, kb.x, kb.y);
            }
        }

        // ---- deferred PV (tile t-1): independent of sacc, fills QK latency ----
        if (kt > 0) {
            #pragma unroll
            for (int ks = 0; ks < 4; ks++) {
                mma_f16(sumacc, pAv[ks][0], pAv[ks][1], pAv[ks][2], pAv[ks][3], ONE2, ONE2);
                #pragma unroll
                for (int df = 0; df < 8; df++) {
                    uint2 vb = Vprev[(ks * 4 + tig) * VP_S + df * 8 + g];
                    mma_f16(oacc[df], pAv[ks][0], pAv[ks][1], pAv[ks][2], pAv[ks][3], vb.x, vb.y);
                }
            }
        }

        if (pm != nullptr) {
            #pragma unroll
            for (int nf = 0; nf < 8; nf++) {
                uint32_t wA = (nf < 4) ? pmA.x : pmA.y;
                uint32_t wB = (nf < 4) ? pmB.x : pmB.y;
                int sh = ((nf & 3) * 8) + 2 * tig;
                if (!((wA >> sh) & 1u)) sacc[nf][0] = -1e9f;
                if (!((wA >> sh) & 2u)) sacc[nf][1] = -1e9f;
                if (!((wB >> sh) & 1u)) sacc[nf][2] = -1e9f;
                if (!((wB >> sh) & 2u)) sacc[nf][3] = -1e9f;
            }
        }

        // ---- online softmax (tile t) ----
        float tm0 = -INFINITY, tm1 = -INFINITY;
        #pragma unroll
        for (int nf = 0; nf < 8; nf++) {
            tm0 = fmaxf(tm0, fmaxf(sacc[nf][0], sacc[nf][1]));
            tm1 = fmaxf(tm1, fmaxf(sacc[nf][2], sacc[nf][3]));
        }
        tm0 = fmaxf(tm0, __shfl_xor_sync(0xffffffffu, tm0, 1));
        tm0 = fmaxf(tm0, __shfl_xor_sync(0xffffffffu, tm0, 2));
        tm1 = fmaxf(tm1, __shfl_xor_sync(0xffffffffu, tm1, 1));
        tm1 = fmaxf(tm1, __shfl_xor_sync(0xffffffffu, tm1, 2));

        float mn0 = fmaxf(mrow[0], tm0), mn1 = fmaxf(mrow[1], tm1);
        float c0 = __expf(mrow[0] - mn0), c1 = __expf(mrow[1] - mn1);
        mrow[0] = mn0; mrow[1] = mn1;
        float nb0 = -mn0 * L2E, nb1 = -mn1 * L2E;

        // pack P(t) into the carry registers (consumed next iteration)
        #pragma unroll
        for (int ks = 0; ks < 4; ks++) {
            int e = 2 * ks, o = 2 * ks + 1;
            pAv[ks][0] = hex2(f2h2(fmaf(sacc[e][0], L2E, nb0), fmaf(sacc[e][1], L2E, nb0)));
            pAv[ks][1] = hex2(f2h2(fmaf(sacc[e][2], L2E, nb1), fmaf(sacc[e][3], L2E, nb1)));
            pAv[ks][2] = hex2(f2h2(fmaf(sacc[o][0], L2E, nb0), fmaf(sacc[o][1], L2E, nb0)));
            pAv[ks][3] = hex2(f2h2(fmaf(sacc[o][2], L2E, nb1), fmaf(sacc[o][3], L2E, nb1)));
        }

        // rescale accumulators to new max (PV(t-1) already added above)
        #pragma unroll
        for (int df = 0; df < 8; df++) {
            oacc[df][0] *= c0; oacc[df][1] *= c0;
            oacc[df][2] *= c1; oacc[df][3] *= c1;
        }
        sumacc[0] *= c0; sumacc[1] *= c0;
        sumacc[2] *= c1; sumacc[3] *= c1;

        Vprev = Vp;
        stage = (stage == 2) ? 0 : stage + 1;
    }

    // ---- final deferred PV (last tile) ----
    #pragma unroll
    for (int ks = 0; ks < 4; ks++) {
        mma_f16(sumacc, pAv[ks][0], pAv[ks][1], pAv[ks][2], pAv[ks][3], ONE2, ONE2);
        #pragma unroll
        for (int df = 0; df < 8; df++) {
            uint2 vb = Vprev[(ks * 4 + tig) * VP_S + df * 8 + g];
            mma_f16(oacc[df], pAv[ks][0], pAv[ks][1], pAv[ks][2], pAv[ks][3], vb.x, vb.y);
        }
    }

    // ---- epilogue: normalize + residual ----
    float inv0 = 1.0f / sumacc[0], inv1 = 1.0f / sumacc[2];
    int r = q0 + wrow + g;
    #pragma unroll
    for (int df = 0; df < 8; df++) {
        size_t idx0 = ((size_t)(b * SEQ + r)) * D_MODEL + h * DKH + df * 8 + 2 * tig;
        size_t idx1 = idx0 + (size_t)8 * D_MODEL;
        float2 ra = *(const float2*)(res + idx0);
        float2 rb = *(const float2*)(res + idx1);
        float2 oa, ob;
        oa.x = ra.x + oacc[df][0] * inv0;
        oa.y = ra.y + oacc[df][1] * inv0;
        ob.x = rb.x + oacc[df][2] * inv1;
        ob.y = rb.y + oacc[df][3] * inv1;
        *(float2*)(out + idx0) = oa;
        *(float2*)(out + idx1) = ob;
    }
}

// ---------------------------------------------------------------------------
// fp16 mma GEMM, fp16 inputs: C = A @ B + bias (+ReLU), out fp32 or fp16.
// Block 128x128, BK=32, 256 threads, warp tile 16x128.
// Double-buffered smem: ONE __syncthreads per k-step.
// ---------------------------------------------------------------------------
#define GA_S 12
#define GB_S 132
#define ASTG (128 * GA_S)
#define BSTG (8 * GB_S)

template<bool RELU, bool RES, bool HOUT>
__global__ __launch_bounds__(256, 2)
void gemm_mma(const uint32_t* __restrict__ A,   // fp16 pairs, [M][K/2]
              const uint32_t* __restrict__ B,   // fp16 pairs, [K][N/2]
              const float* __restrict__ bias,
              const float* __restrict__ res,
              void* __restrict__ Cv,
              int M, int N, int K) {
    __shared__ uint2 Apb[2 * ASTG];
    __shared__ uint2 Bpb[2 * BSTG];

    const int n0   = blockIdx.x * 128;
    const int m0   = blockIdx.y * 128;
    const int tid  = threadIdx.x;
    const int lane = tid & 31;
    const int warp = tid >> 5;
    const int g    = lane >> 2;
    const int tig  = lane & 3;
    const int wrow = warp * 16;
    const int KU   = K / 2, NU = N / 2;

    const int ar  = tid >> 1, ah = tid & 1;
    const int bcc = tid & 31;
    const int bks = (tid >> 7) & 1, btr = (tid >> 5) & 3;
    const int br0 = bks * 16 + 2 * btr;

    uint4 af[2];
    uint2 bf[4];

    auto ldg_tiles = [&](int k0) {
        const uint32_t* as_ = A + (size_t)(m0 + ar) * KU + k0 / 2 + ah * 8;
        af[0] = *(const uint4*)as_;
        af[1] = *(const uint4*)(as_ + 4);
        const uint32_t* bs_ = B + (size_t)(k0 + br0) * NU + n0 / 2 + bcc * 2;
        bf[0] = *(const uint2*)bs_;
        bf[1] = *(const uint2*)(bs_ + (size_t)1 * NU);
        bf[2] = *(const uint2*)(bs_ + (size_t)8 * NU);
        bf[3] = *(const uint2*)(bs_ + (size_t)9 * NU);
    };
    auto sts_tiles = [&](uint2* Ap, uint2* Bp) {
        uint4* da = (uint4*)(Ap + ar * GA_S + ah * 4);
        da[0] = make_uint4(af[0].x, af[1].x, af[0].y, af[1].y);
        da[1] = make_uint4(af[0].z, af[1].z, af[0].w, af[1].w);
        uint4* db = (uint4*)(Bp + (bks * 4 + btr) * GB_S + bcc * 4);
        db[0] = make_uint4(h2lo(bf[0].x, bf[1].x), h2lo(bf[2].x, bf[3].x),
                           h2hi(bf[0].x, bf[1].x), h2hi(bf[2].x, bf[3].x));
        db[1] = make_uint4(h2lo(bf[0].y, bf[1].y), h2lo(bf[2].y, bf[3].y),
                           h2hi(bf[0].y, bf[1].y), h2hi(bf[2].y, bf[3].y));
    };

    float acc[16][4];
    #pragma unroll
    for (int i = 0; i < 16; i++)
        #pragma unroll
        for (int j = 0; j < 4; j++) acc[i][j] = 0.0f;

    ldg_tiles(0);

    int it = 0;
    for (int k0 = 0; k0 < K; k0 += 32, it++) {
        uint2* Ap = Apb + (it & 1) * ASTG;
        uint2* Bp = Bpb + (it & 1) * BSTG;
        sts_tiles(Ap, Bp);
        __syncthreads();   // stage ready; prev compute on other buffer done
        if (k0 + 32 < K) ldg_tiles(k0 + 32);

        #pragma unroll
        for (int ks = 0; ks < 2; ks++) {
            uint2 aa = Ap[(wrow + g)     * GA_S + ks * 4 + tig];
            uint2 ab = Ap[(wrow + 8 + g) * GA_S + ks * 4 + tig];
            #pragma unroll
            for (int nf = 0; nf < 16; nf++) {
                uint2 bb = Bp[(ks * 4 + tig) * GB_S + nf * 8 + g];
                mma_f16(acc[nf], aa.x, ab.x, aa.y, ab.y, bb.x, bb.y);
            }
        }
    }

    const int row0 = m0 + wrow + g;
    #pragma unroll
    for (int nf = 0; nf < 16; nf++) {
        int col = n0 + nf * 8 + 2 * tig;
        float2 bi = *(const float2*)(bias + col);
        float2 va, vb;
        va.x = acc[nf][0] + bi.x; va.y = acc[nf][1] + bi.y;
        vb.x = acc[nf][2] + bi.x; vb.y = acc[nf][3] + bi.y;
        if (RELU) {
            va.x = fmaxf(va.x, 0.0f); va.y = fmaxf(va.y, 0.0f);
            vb.x = fmaxf(vb.x, 0.0f); vb.y = fmaxf(vb.y, 0.0f);
        }
        if (HOUT) {
            uint32_t* C = (uint32_t*)Cv;
            C[((size_t)row0 * N + col) / 2]       = f2h2(va.x, va.y);
            C[((size_t)(row0 + 8) * N + col) / 2] = f2h2(vb.x, vb.y);
        } else {
            float* C = (float*)Cv;
            size_t idx0 = (size_t)row0 * N + col;
            size_t idx1 = idx0 + (size_t)8 * N;
            if (RES) {
                float2 ra = *(const float2*)(res + idx0);
                float2 rb = *(const float2*)(res + idx1);
                va.x += ra.x; va.y += ra.y;
                vb.x += rb.x; vb.y += rb.y;
            }
            *(float2*)(C + idx0) = va;
            *(float2*)(C + idx1) = vb;
        }
    }
}

// ---------------------------------------------------------------------------
extern "C" void kernel_launch(void* const* d_in, const int* in_sizes, int n_in,
                              void* d_out, int out_size) {
    const float* x    = (const float*)d_in[0];
    const float* enc  = (const float*)d_in[1];
    const int*   mask = (const int*)  d_in[2];
    const float* ln1g = (const float*)d_in[3];
    const float* ln1b = (const float*)d_in[4];
    const float* ln2g = (const float*)d_in[5];
    const float* ln2b = (const float*)d_in[6];
    const float* ln3g = (const float*)d_in[7];
    const float* ln3b = (const float*)d_in[8];
    const float* W1   = (const float*)d_in[9];
    const float* b1   = (const float*)d_in[10];
    const float* W2   = (const float*)d_in[11];
    const float* b2   = (const float*)d_in[12];
    float* out = (float*)d_out;

    float *gx;
    uint32_t *gxnh, *gench, *ghh, *gw1h, *gw2h, *gpm;
    cudaGetSymbolAddress((void**)&gx,    g_x);
    cudaGetSymbolAddress((void**)&gxnh,  g_xnh);
    cudaGetSymbolAddress((void**)&gench, g_ench);
    cudaGetSymbolAddress((void**)&ghh,   g_hh);
    cudaGetSymbolAddress((void**)&gw1h,  g_w1h);
    cudaGetSymbolAddress((void**)&gw2h,  g_w2h);
    cudaGetSymbolAddress((void**)&gpm,   g_pm);

    cudaFuncSetAttribute(attn_mma_kernel,
                         cudaFuncAttributeMaxDynamicSharedMemorySize,
                         ATTN_SMEM_BYTES);

    dim3 attn_grid(SEQ / BM, HEADS, BATCH);

    // one-time conversions (per launch)
    pack_mask_kernel<<<(BATCH * SEQ * SEQ) / 1024 / 8, 256>>>(mask, gpm);
    cvt_h_kernel<<<4096, 256>>>(enc, gench, NROWS * D_MODEL / 4);
    cvt_h_kernel<<<512,  256>>>(W1,  gw1h,  D_MODEL * D_FF / 4);
    cvt_h_kernel<<<512,  256>>>(W2,  gw2h,  D_FF * D_MODEL / 4);

    // 1) x1 = LN1(x); x' = x + selfattn(x1, mask)
    ln_kernel<<<NROWS / 8, 256>>>(x, ln1g, ln1b, gxnh);
    attn_mma_kernel<<<attn_grid, 256, ATTN_SMEM_BYTES>>>(gxnh, gxnh, gpm, x, gx);

    // 2) x1 = LN2(x'); x'' = x' + crossattn(x1, enc)
    ln_kernel<<<NROWS / 8, 256>>>(gx, ln2g, ln2b, gxnh);
    attn_mma_kernel<<<attn_grid, 256, ATTN_SMEM_BYTES>>>(gxnh, gench, nullptr, gx, gx);

    // 3) x1 = LN3(x''); out = x'' + relu(x1 W1 + b1) W2 + b2
    ln_kernel<<<NROWS / 8, 256>>>(gx, ln3g, ln3b, gxnh);
    gemm_mma<true,  false, true ><<<dim3(D_FF / 128,    NROWS / 128), 256>>>(
        gxnh, gw1h, b1, nullptr, ghh, NROWS, D_FF, D_MODEL);
    gemm_mma<false, true,  false><<<dim3(D_MODEL / 128, NROWS / 128), 256>>>(
        ghh, gw2h, b2, gx, out, NROWS, D_MODEL, D_FF);
}

// round 16
// speedup vs baseline: 1.0992x; 1.0992x over previous
#include <cuda_runtime.h>
#include <cuda_fp16.h>
#include <math.h>
#include <stdint.h>

#define D_MODEL 512
#define HEADS   8
#define DKH     64
#define SEQ     2048
#define BATCH   4
#define D_FF    1024
#define NROWS   (BATCH*SEQ)   // 8192

// Scratch (static device arrays — no allocation at runtime)
__device__ float    g_x  [NROWS * D_MODEL];          // residual stream (fp32)
__device__ uint32_t g_xnh[NROWS * D_MODEL / 2];      // LN output, fp16 pairs
__device__ uint32_t g_ench[NROWS * D_MODEL / 2];     // encoder_output fp16
__device__ uint32_t g_hh [NROWS * D_FF / 2];         // FFN hidden fp16
__device__ uint32_t g_w1h[D_MODEL * D_FF / 2];       // W1 fp16
__device__ uint32_t g_w2h[D_FF * D_MODEL / 2];       // W2 fp16
__device__ uint32_t g_pm [BATCH * SEQ * (SEQ / 32)]; // packed mask bits (2MB)

// ---------------------------------------------------------------------------
// helpers
// ---------------------------------------------------------------------------
__device__ __forceinline__ uint32_t f2h2(float lo, float hi) {
    __half2 h = __floats2half2_rn(lo, hi);
    return *(uint32_t*)&h;
}
__device__ __forceinline__ uint32_t h2lo(uint32_t a, uint32_t b) {  // {a.h0,b.h0}
    return __byte_perm(a, b, 0x5410);
}
__device__ __forceinline__ uint32_t h2hi(uint32_t a, uint32_t b) {  // {a.h1,b.h1}
    return __byte_perm(a, b, 0x7632);
}
__device__ __forceinline__ uint32_t hex2(uint32_t t) {   // 2^t per fp16 lane
    uint32_t r;
    asm("ex2.approx.f16x2 %0, %1;" : "=r"(r) : "r"(t));
    return r;
}

__device__ __forceinline__ void mma_f16(float c[4],
                                        uint32_t a0, uint32_t a1, uint32_t a2, uint32_t a3,
                                        uint32_t b0, uint32_t b1) {
    asm volatile(
        "mma.sync.aligned.m16n8k16.row.col.f32.f16.f16.f32 "
        "{%0,%1,%2,%3}, {%4,%5,%6,%7}, {%8,%9}, {%0,%1,%2,%3};\n"
        : "+f"(c[0]), "+f"(c[1]), "+f"(c[2]), "+f"(c[3])
        : "r"(a0), "r"(a1), "r"(a2), "r"(a3), "r"(b0), "r"(b1));
}

#define L2E 1.4426950408889634f
#define ONE2 0x3C003C00u   // fp16 {1.0, 1.0}

// ---------------------------------------------------------------------------
// fp32 -> fp16 pair converter (grid-stride, float4 -> uint2)
// ---------------------------------------------------------------------------
__global__ void cvt_h_kernel(const float* __restrict__ x,
                             uint32_t* __restrict__ yh, int n4) {
    int i = blockIdx.x * blockDim.x + threadIdx.x;
    int stride = gridDim.x * blockDim.x;
    for (; i < n4; i += stride) {
        float4 v = ((const float4*)x)[i];
        ((uint2*)yh)[i] = make_uint2(f2h2(v.x, v.y), f2h2(v.z, v.w));
    }
}

// ---------------------------------------------------------------------------
// Mask packing: bit j of pm[i/32] = (mask[i] != 0). 1 warp handles 1024 ints.
// ---------------------------------------------------------------------------
__device__ __forceinline__ uint32_t spread4(uint32_t x) {
    x &= 0xFFu;
    x = (x | (x << 12)) & 0x000F000Fu;
    x = (x | (x << 6))  & 0x03030303u;
    x = (x | (x << 3))  & 0x11111111u;
    return x;
}

__global__ void pack_mask_kernel(const int* __restrict__ mask,
                                 uint32_t* __restrict__ pm) {
    int w    = (blockIdx.x * blockDim.x + threadIdx.x) >> 5;
    int lane = threadIdx.x & 31;
    size_t base = (size_t)w * 1024;
    #pragma unroll
    for (int it = 0; it < 8; it++) {
        int4 v = *(const int4*)(mask + base + it * 128 + lane * 4);
        uint32_t b0 = __ballot_sync(0xffffffffu, v.x != 0);
        uint32_t b1 = __ballot_sync(0xffffffffu, v.y != 0);
        uint32_t b2 = __ballot_sync(0xffffffffu, v.z != 0);
        uint32_t b3 = __ballot_sync(0xffffffffu, v.w != 0);
        if (lane < 4) {
            uint32_t word =  spread4(b0 >> (8 * lane))
                          | (spread4(b1 >> (8 * lane)) << 1)
                          | (spread4(b2 >> (8 * lane)) << 2)
                          | (spread4(b3 >> (8 * lane)) << 3);
            pm[base / 32 + it * 4 + lane] = word;
        }
    }
}

// ---------------------------------------------------------------------------
// LayerNorm: one WARP per row, shuffle-only reduction, emits fp16 pairs.
// ---------------------------------------------------------------------------
__global__ __launch_bounds__(256)
void ln_kernel(const float* __restrict__ x,
               const float* __restrict__ gamma,
               const float* __restrict__ beta,
               uint32_t* __restrict__ yh) {
    const int lane = threadIdx.x & 31;
    const int row  = blockIdx.x * 8 + (threadIdx.x >> 5);
    const float4* xr = (const float4*)(x + (size_t)row * D_MODEL);

    float4 v[4];
    float s = 0.0f, ss = 0.0f;
    #pragma unroll
    for (int i = 0; i < 4; i++) {
        v[i] = xr[lane + 32 * i];
        s  += v[i].x + v[i].y + v[i].z + v[i].w;
        ss += v[i].x*v[i].x + v[i].y*v[i].y + v[i].z*v[i].z + v[i].w*v[i].w;
    }
    #pragma unroll
    for (int o = 16; o > 0; o >>= 1) {
        s  += __shfl_xor_sync(0xffffffffu, s,  o);
        ss += __shfl_xor_sync(0xffffffffu, ss, o);
    }
    float mu  = s * (1.0f / D_MODEL);
    float var = ss * (1.0f / D_MODEL) - mu * mu;
    float rs  = rsqrtf(var + 1e-5f);

    uint2* yr = (uint2*)(yh + (size_t)row * (D_MODEL / 2));
    #pragma unroll
    for (int i = 0; i < 4; i++) {
        float4 g4 = ((const float4*)gamma)[lane + 32 * i];
        float4 b4 = ((const float4*)beta)[lane + 32 * i];
        float o0 = (v[i].x - mu) * rs * g4.x + b4.x;
        float o1 = (v[i].y - mu) * rs * g4.y + b4.y;
        float o2 = (v[i].z - mu) * rs * g4.z + b4.z;
        float o3 = (v[i].w - mu) * rs * g4.w + b4.w;
        yr[lane + 32 * i] = make_uint2(f2h2(o0, o1), f2h2(o2, o3));
    }
}

// ---------------------------------------------------------------------------
// Flash attention, fp16 mma. BM=128, 256 threads, warp tile 16x64.
// R13 schedule (validated, 428us) + LDG hoisted above the barrier.
// ---------------------------------------------------------------------------
#define BM    128
#define QP_S  20
#define KP_S  20
#define VP_S  68
#define KSTG  (64*KP_S + 16*VP_S)    // uint2 per K/V stage
#define ATTN_SMEM_BYTES ((128*QP_S + 2*KSTG) * 8)
#define ROWU  (D_MODEL / 2)          // u32 per row (256)

__global__ __launch_bounds__(256, 2)
void attn_mma_kernel(const uint32_t* __restrict__ Qh,
                     const uint32_t* __restrict__ KVh,
                     const uint32_t* __restrict__ pm,   // packed mask, may be null
                     const float* __restrict__ res,
                     float* __restrict__ out) {
    extern __shared__ uint2 sm2[];
    uint2* Qp     = sm2;
    uint2* KVbase = Qp + 128 * QP_S;

    const int q0   = blockIdx.x * BM;
    const int h    = blockIdx.y;
    const int b    = blockIdx.z;
    const int tid  = threadIdx.x;
    const int lane = tid & 31;
    const int warp = tid >> 5;
    const int g    = lane >> 2;
    const int tig  = lane & 3;
    const int wrow = warp * 16;

    const __half2 qscale = __float2half2_rn(0.125f);   // exact (power of 2)

    #pragma unroll
    for (int it = 0; it < 2; it++) {
        int i = tid + it * 256;
        int r = i >> 2, cc = i & 3;
        const uint32_t* src = Qh + (size_t)(b * SEQ + q0 + r) * ROWU + h * 32 + cc * 8;
        uint4 u0 = *(const uint4*)src;
        uint4 u1 = *(const uint4*)(src + 4);
        uint32_t u[8] = {u0.x, u0.y, u0.z, u0.w, u1.x, u1.y, u1.z, u1.w};
        #pragma unroll
        for (int k = 0; k < 8; k++) {
            __half2 hv = __hmul2(*(__half2*)&u[k], qscale);
            u[k] = *(uint32_t*)&hv;
        }
        uint4* d4 = (uint4*)(Qp + r * QP_S + cc * 4);
        d4[0] = make_uint4(u[0], u[4], u[1], u[5]);
        d4[1] = make_uint4(u[2], u[6], u[3], u[7]);
    }

    float oacc[8][4];
    #pragma unroll
    for (int i = 0; i < 8; i++)
        #pragma unroll
        for (int j = 0; j < 4; j++) oacc[i][j] = 0.0f;
    float sumacc[4] = {0.0f, 0.0f, 0.0f, 0.0f};

    float mrow[2] = {-INFINITY, -INFINITY};

    const int kr  = tid >> 2,  kcc = tid & 3;
    const int vcc = tid & 15;
    const int vks = (tid >> 6) & 3, vtr = (tid >> 4) & 3;
    const int vr0 = vks * 16 + 2 * vtr;

    uint4 kf[2];
    uint2 vf[4];

    auto ldg_tile = [&](int k0) {
        const uint32_t* ks_ = KVh + (size_t)(b * SEQ + k0 + kr) * ROWU + h * 32 + kcc * 8;
        kf[0] = *(const uint4*)ks_;
        kf[1] = *(const uint4*)(ks_ + 4);
        const uint32_t* vs_ = KVh + (size_t)(b * SEQ + k0 + vr0) * ROWU + h * 32 + vcc * 2;
        vf[0] = *(const uint2*)vs_;
        vf[1] = *(const uint2*)(vs_ + (size_t)1 * ROWU);
        vf[2] = *(const uint2*)(vs_ + (size_t)8 * ROWU);
        vf[3] = *(const uint2*)(vs_ + (size_t)9 * ROWU);
    };
    auto sts_tile = [&](uint2* Kp, uint2* Vp) {
        uint4* dk = (uint4*)(Kp + kr * KP_S + kcc * 4);
        dk[0] = make_uint4(kf[0].x, kf[1].x, kf[0].y, kf[1].y);
        dk[1] = make_uint4(kf[0].z, kf[1].z, kf[0].w, kf[1].w);
        uint4* dv = (uint4*)(Vp + (vks * 4 + vtr) * VP_S + vcc * 4);
        dv[0] = make_uint4(h2lo(vf[0].x, vf[1].x), h2lo(vf[2].x, vf[3].x),
                           h2hi(vf[0].x, vf[1].x), h2hi(vf[2].x, vf[3].x));
        dv[1] = make_uint4(h2lo(vf[0].y, vf[1].y), h2lo(vf[2].y, vf[3].y),
                           h2hi(vf[0].y, vf[1].y), h2hi(vf[2].y, vf[3].y));
    };

    ldg_tile(0);

    for (int kt = 0; kt < SEQ / 64; kt++) {
        uint2* Kp = KVbase + (kt & 1) * KSTG;
        uint2* Vp = Kp + 64 * KP_S;
        sts_tile(Kp, Vp);
        if (kt + 1 < SEQ / 64) ldg_tile((kt + 1) * 64);   // regs free post-sts; issue before barrier
        __syncthreads();

        uint2 pmA, pmB;
        if (pm != nullptr) {
            const uint32_t* pr = pm + ((size_t)(b * SEQ + q0 + wrow + g)) * (SEQ / 32) + kt * 2;
            pmA = *(const uint2*)pr;
            pmB = *(const uint2*)(pr + (size_t)8 * (SEQ / 32));
        }

        // ---- S = Q K^T ----
        float sacc[8][4];
        #pragma unroll
        for (int i = 0; i < 8; i++)
            #pragma unroll
            for (int j = 0; j < 4; j++) sacc[i][j] = 0.0f;

        #pragma unroll
        for (int ks = 0; ks < 4; ks++) {
            uint2 qa = Qp[(wrow + g)     * QP_S + ks * 4 + tig];
            uint2 qb = Qp[(wrow + 8 + g) * QP_S + ks * 4 + tig];
            #pragma unroll
            for (int nf = 0; nf < 8; nf++) {
                uint2 kb = Kp[(nf * 8 + g) * KP_S + ks * 4 + tig];
                mma_f16(sacc[nf], qa.x, qb.x, qa.y, qb.y, kb.x, kb.y);
            }
        }

        if (pm != nullptr) {
            #pragma unroll
            for (int nf = 0; nf < 8; nf++) {
                uint32_t wA = (nf < 4) ? pmA.x : pmA.y;
                uint32_t wB = (nf < 4) ? pmB.x : pmB.y;
                int sh = ((nf & 3) * 8) + 2 * tig;
                if (!((wA >> sh) & 1u)) sacc[nf][0] = -1e9f;
                if (!((wA >> sh) & 2u)) sacc[nf][1] = -1e9f;
                if (!((wB >> sh) & 1u)) sacc[nf][2] = -1e9f;
                if (!((wB >> sh) & 2u)) sacc[nf][3] = -1e9f;
            }
        }

        // ---- online softmax ----
        float tm0 = -INFINITY, tm1 = -INFINITY;
        #pragma unroll
        for (int nf = 0; nf < 8; nf++) {
            tm0 = fmaxf(tm0, fmaxf(sacc[nf][0], sacc[nf][1]));
            tm1 = fmaxf(tm1, fmaxf(sacc[nf][2], sacc[nf][3]));
        }
        tm0 = fmaxf(tm0, __shfl_xor_sync(0xffffffffu, tm0, 1));
        tm0 = fmaxf(tm0, __shfl_xor_sync(0xffffffffu, tm0, 2));
        tm1 = fmaxf(tm1, __shfl_xor_sync(0xffffffffu, tm1, 1));
        tm1 = fmaxf(tm1, __shfl_xor_sync(0xffffffffu, tm1, 2));

        float mn0 = fmaxf(mrow[0], tm0), mn1 = fmaxf(mrow[1], tm1);
        float c0 = __expf(mrow[0] - mn0), c1 = __expf(mrow[1] - mn1);
        mrow[0] = mn0; mrow[1] = mn1;
        float nb0 = -mn0 * L2E, nb1 = -mn1 * L2E;

        uint32_t pA[4][4];
        #pragma unroll
        for (int ks = 0; ks < 4; ks++) {
            int e = 2 * ks, o = 2 * ks + 1;
            pA[ks][0] = hex2(f2h2(fmaf(sacc[e][0], L2E, nb0), fmaf(sacc[e][1], L2E, nb0)));
            pA[ks][1] = hex2(f2h2(fmaf(sacc[e][2], L2E, nb1), fmaf(sacc[e][3], L2E, nb1)));
            pA[ks][2] = hex2(f2h2(fmaf(sacc[o][0], L2E, nb0), fmaf(sacc[o][1], L2E, nb0)));
            pA[ks][3] = hex2(f2h2(fmaf(sacc[o][2], L2E, nb1), fmaf(sacc[o][3], L2E, nb1)));
        }

        #pragma unroll
        for (int df = 0; df < 8; df++) {
            oacc[df][0] *= c0; oacc[df][1] *= c0;
            oacc[df][2] *= c1; oacc[df][3] *= c1;
        }
        sumacc[0] *= c0; sumacc[1] *= c0;
        sumacc[2] *= c1; sumacc[3] *= c1;

        #pragma unroll
        for (int ks = 0; ks < 4; ks++) {
            mma_f16(sumacc, pA[ks][0], pA[ks][1], pA[ks][2], pA[ks][3], ONE2, ONE2);
            #pragma unroll
            for (int df = 0; df < 8; df++) {
                uint2 vb = Vp[(ks * 4 + tig) * VP_S + df * 8 + g];
                mma_f16(oacc[df], pA[ks][0], pA[ks][1], pA[ks][2], pA[ks][3], vb.x, vb.y);
            }
        }
    }

    float inv0 = 1.0f / sumacc[0], inv1 = 1.0f / sumacc[2];
    int r = q0 + wrow + g;
    #pragma unroll
    for (int df = 0; df < 8; df++) {
        size_t idx0 = ((size_t)(b * SEQ + r)) * D_MODEL + h * DKH + df * 8 + 2 * tig;
        size_t idx1 = idx0 + (size_t)8 * D_MODEL;
        float2 ra = *(const float2*)(res + idx0);
        float2 rb = *(const float2*)(res + idx1);
        float2 oa, ob;
        oa.x = ra.x + oacc[df][0] * inv0;
        oa.y = ra.y + oacc[df][1] * inv0;
        ob.x = rb.x + oacc[df][2] * inv1;
        ob.y = rb.y + oacc[df][3] * inv1;
        *(float2*)(out + idx0) = oa;
        *(float2*)(out + idx1) = ob;
    }
}

// ---------------------------------------------------------------------------
// fp16 mma GEMM: C = A @ B + bias (+ReLU), out fp32 or fp16.
// Block 128x128, BK=64, 256 threads, warp tile 16x128.
// Double-buffered dynamic smem, ONE barrier per k-step, LDG hoisted.
// ---------------------------------------------------------------------------
#define GA_S 20    // uint2 per A row (16 + pad 4) — same pattern as QP_S
#define GB_S 132   // uint2 per B group-row (128 + pad 4)
#define ASTG (128 * GA_S)   // 2560 uint2
#define BSTG (16 * GB_S)    // 2112 uint2
#define GEMM_SMEM_BYTES ((2 * ASTG + 2 * BSTG) * 8)   // 74752 B

template<bool RELU, bool RES, bool HOUT>
__global__ __launch_bounds__(256, 2)
void gemm_mma(const uint32_t* __restrict__ A,   // fp16 pairs, [M][K/2]
              const uint32_t* __restrict__ B,   // fp16 pairs, [K][N/2]
              const float* __restrict__ bias,
              const float* __restrict__ res,
              void* __restrict__ Cv,
              int M, int N, int K) {
    extern __shared__ uint2 gsm[];
    uint2* Apb = gsm;
    uint2* Bpb = gsm + 2 * ASTG;

    const int n0   = blockIdx.x * 128;
    const int m0   = blockIdx.y * 128;
    const int tid  = threadIdx.x;
    const int lane = tid & 31;
    const int warp = tid >> 5;
    const int g    = lane >> 2;
    const int tig  = lane & 3;
    const int wrow = warp * 16;
    const int KU   = K / 2, NU = N / 2;

    // loader coords
    const int ar  = tid >> 1, ah = tid & 1;                 // A: row, 32-col half
    const int bcc = tid & 31;                               // B: col chunk (4 cols)
    const int bks = (tid >> 7) & 1, btr = (tid >> 5) & 3;   // B: k16-sub, row-in-group
    const int br0 = bks * 16 + 2 * btr;

    uint4 af[4];        // A: 32 cols = 16 u32
    uint2 bf[2][4];     // B: 2 subs x 4 rows x 1 uint2

    auto ldg_tiles = [&](int k0) {
        const uint4* as_ = (const uint4*)(A + (size_t)(m0 + ar) * KU + k0 / 2 + ah * 16);
        af[0] = as_[0]; af[1] = as_[1]; af[2] = as_[2]; af[3] = as_[3];
        #pragma unroll
        for (int s = 0; s < 2; s++) {
            const uint32_t* bs_ = B + (size_t)(k0 + 32 * s + br0) * NU + n0 / 2 + bcc * 2;
            bf[s][0] = *(const uint2*)bs_;
            bf[s][1] = *(const uint2*)(bs_ + (size_t)1 * NU);
            bf[s][2] = *(const uint2*)(bs_ + (size_t)8 * NU);
            bf[s][3] = *(const uint2*)(bs_ + (size_t)9 * NU);
        }
    };
    auto sts_tiles = [&](uint2* Ap, uint2* Bp) {
        #pragma unroll
        for (int c = 0; c < 2; c++) {   // two k16 chunks: indices 2*ah + c
            uint4 u0 = af[2 * c], u1 = af[2 * c + 1];
            uint4* da = (uint4*)(Ap + ar * GA_S + (2 * ah + c) * 4);
            da[0] = make_uint4(u0.x, u1.x, u0.y, u1.y);
            da[1] = make_uint4(u0.z, u1.z, u0.w, u1.w);
        }
        #pragma unroll
        for (int s = 0; s < 2; s++) {
            uint4* db = (uint4*)(Bp + (size_t)(8 * s + 4 * bks + btr) * GB_S + bcc * 4);
            db[0] = make_uint4(h2lo(bf[s][0].x, bf[s][1].x), h2lo(bf[s][2].x, bf[s][3].x),
                               h2hi(bf[s][0].x, bf[s][1].x), h2hi(bf[s][2].x, bf[s][3].x));
            db[1] = make_uint4(h2lo(bf[s][0].y, bf[s][1].y), h2lo(bf[s][2].y, bf[s][3].y),
                               h2hi(bf[s][0].y, bf[s][1].y), h2hi(bf[s][2].y, bf[s][3].y));
        }
    };

    float acc[16][4];
    #pragma unroll
    for (int i = 0; i < 16; i++)
        #pragma unroll
        for (int j = 0; j < 4; j++) acc[i][j] = 0.0f;

    ldg_tiles(0);

    int it = 0;
    for (int k0 = 0; k0 < K; k0 += 64, it++) {
        uint2* Ap = Apb + (it & 1) * ASTG;
        uint2* Bp = Bpb + (it & 1) * BSTG;
        sts_tiles(Ap, Bp);
        if (k0 + 64 < K) ldg_tiles(k0 + 64);   // before barrier: regs free, max cover
        __syncthreads();   // stage ready; prev compute on other buffer done

        #pragma unroll
        for (int ks = 0; ks < 4; ks++) {
            uint2 aa = Ap[(wrow + g)     * GA_S + ks * 4 + tig];
            uint2 ab = Ap[(wrow + 8 + g) * GA_S + ks * 4 + tig];
            #pragma unroll
            for (int nf = 0; nf < 16; nf++) {
                uint2 bb = Bp[(ks * 4 + tig) * GB_S + nf * 8 + g];
                mma_f16(acc[nf], aa.x, ab.x, aa.y, ab.y, bb.x, bb.y);
            }
        }
    }

    const int row0 = m0 + wrow + g;
    #pragma unroll
    for (int nf = 0; nf < 16; nf++) {
        int col = n0 + nf * 8 + 2 * tig;
        float2 bi = *(const float2*)(bias + col);
        float2 va, vb;
        va.x = acc[nf][0] + bi.x; va.y = acc[nf][1] + bi.y;
        vb.x = acc[nf][2] + bi.x; vb.y = acc[nf][3] + bi.y;
        if (RELU) {
            va.x = fmaxf(va.x, 0.0f); va.y = fmaxf(va.y, 0.0f);
            vb.x = fmaxf(vb.x, 0.0f); vb.y = fmaxf(vb.y, 0.0f);
        }
        if (HOUT) {
            uint32_t* C = (uint32_t*)Cv;
            C[((size_t)row0 * N + col) / 2]       = f2h2(va.x, va.y);
            C[((size_t)(row0 + 8) * N + col) / 2] = f2h2(vb.x, vb.y);
        } else {
            float* C = (float*)Cv;
            size_t idx0 = (size_t)row0 * N + col;
            size_t idx1 = idx0 + (size_t)8 * N;
            if (RES) {
                float2 ra = *(const float2*)(res + idx0);
                float2 rb = *(const float2*)(res + idx1);
                va.x += ra.x; va.y += ra.y;
                vb.x += rb.x; vb.y += rb.y;
            }
            *(float2*)(C + idx0) = va;
            *(float2*)(C + idx1) = vb;
        }
    }
}

// ---------------------------------------------------------------------------
extern "C" void kernel_launch(void* const* d_in, const int* in_sizes, int n_in,
                              void* d_out, int out_size) {
    const float* x    = (const float*)d_in[0];
    const float* enc  = (const float*)d_in[1];
    const int*   mask = (const int*)  d_in[2];
    const float* ln1g = (const float*)d_in[3];
    const float* ln1b = (const float*)d_in[4];
    const float* ln2g = (const float*)d_in[5];
    const float* ln2b = (const float*)d_in[6];
    const float* ln3g = (const float*)d_in[7];
    const float* ln3b = (const float*)d_in[8];
    const float* W1   = (const float*)d_in[9];
    const float* b1   = (const float*)d_in[10];
    const float* W2   = (const float*)d_in[11];
    const float* b2   = (const float*)d_in[12];
    float* out = (float*)d_out;

    float *gx;
    uint32_t *gxnh, *gench, *ghh, *gw1h, *gw2h, *gpm;
    cudaGetSymbolAddress((void**)&gx,    g_x);
    cudaGetSymbolAddress((void**)&gxnh,  g_xnh);
    cudaGetSymbolAddress((void**)&gench, g_ench);
    cudaGetSymbolAddress((void**)&ghh,   g_hh);
    cudaGetSymbolAddress((void**)&gw1h,  g_w1h);
    cudaGetSymbolAddress((void**)&gw2h,  g_w2h);
    cudaGetSymbolAddress((void**)&gpm,   g_pm);

    cudaFuncSetAttribute(attn_mma_kernel,
                         cudaFuncAttributeMaxDynamicSharedMemorySize,
                         ATTN_SMEM_BYTES);
    cudaFuncSetAttribute(gemm_mma<true,  false, true >,
                         cudaFuncAttributeMaxDynamicSharedMemorySize,
                         GEMM_SMEM_BYTES);
    cudaFuncSetAttribute(gemm_mma<false, true,  false>,
                         cudaFuncAttributeMaxDynamicSharedMemorySize,
                         GEMM_SMEM_BYTES);

    dim3 attn_grid(SEQ / BM, HEADS, BATCH);

    // one-time conversions (per launch)
    pack_mask_kernel<<<(BATCH * SEQ * SEQ) / 1024 / 8, 256>>>(mask, gpm);
    cvt_h_kernel<<<4096, 256>>>(enc, gench, NROWS * D_MODEL / 4);
    cvt_h_kernel<<<512,  256>>>(W1,  gw1h,  D_MODEL * D_FF / 4);
    cvt_h_kernel<<<512,  256>>>(W2,  gw2h,  D_FF * D_MODEL / 4);

    // 1) x1 = LN1(x); x' = x + selfattn(x1, mask)
    ln_kernel<<<NROWS / 8, 256>>>(x, ln1g, ln1b, gxnh);
    attn_mma_kernel<<<attn_grid, 256, ATTN_SMEM_BYTES>>>(gxnh, gxnh, gpm, x, gx);

    // 2) x1 = LN2(x'); x'' = x' + crossattn(x1, enc)
    ln_kernel<<<NROWS / 8, 256>>>(gx, ln2g, ln2b, gxnh);
    attn_mma_kernel<<<attn_grid, 256, ATTN_SMEM_BYTES>>>(gxnh, gench, nullptr, gx, gx);

    // 3) x1 = LN3(x''); out = x'' + relu(x1 W1 + b1) W2 + b2
    ln_kernel<<<NROWS / 8, 256>>>(gx, ln3g, ln3b, gxnh);
    gemm_mma<true,  false, true ><<<dim3(D_FF / 128,    NROWS / 128), 256, GEMM_SMEM_BYTES>>>(
        gxnh, gw1h, b1, nullptr, ghh, NROWS, D_FF, D_MODEL);
    gemm_mma<false, true,  false><<<dim3(D_MODEL / 128, NROWS / 128), 256, GEMM_SMEM_BYTES>>>(
        ghh, gw2h, b2, gx, out, NROWS, D_MODEL, D_FF);
}

// round 17
// speedup vs baseline: 1.2397x; 1.1278x over previous
#include <cuda_runtime.h>
#include <cuda_fp16.h>
#include <math.h>
#include <stdint.h>

#define D_MODEL 512
#define HEADS   8
#define DKH     64
#define SEQ     2048
#define BATCH   4
#define D_FF    1024
#define NROWS   (BATCH*SEQ)   // 8192

// Scratch (static device arrays — no allocation at runtime)
__device__ float    g_x  [NROWS * D_MODEL];          // residual stream (fp32)
__device__ uint32_t g_xnh[NROWS * D_MODEL / 2];      // LN output, fp16 pairs
__device__ uint32_t g_ench[NROWS * D_MODEL / 2];     // encoder_output fp16
__device__ uint32_t g_hh [NROWS * D_FF / 2];         // FFN hidden fp16
__device__ uint32_t g_w1h[D_MODEL * D_FF / 2];       // W1 fp16
__device__ uint32_t g_w2h[D_FF * D_MODEL / 2];       // W2 fp16
__device__ uint32_t g_pm [BATCH * SEQ * (SEQ / 32)]; // packed mask bits (2MB)

// ---------------------------------------------------------------------------
// helpers
// ---------------------------------------------------------------------------
__device__ __forceinline__ uint32_t f2h2(float lo, float hi) {
    __half2 h = __floats2half2_rn(lo, hi);
    return *(uint32_t*)&h;
}
__device__ __forceinline__ uint32_t h2lo(uint32_t a, uint32_t b) {  // {a.h0,b.h0}
    return __byte_perm(a, b, 0x5410);
}
__device__ __forceinline__ uint32_t h2hi(uint32_t a, uint32_t b) {  // {a.h1,b.h1}
    return __byte_perm(a, b, 0x7632);
}
__device__ __forceinline__ uint32_t hex2(uint32_t t) {   // 2^t per fp16 lane
    uint32_t r;
    asm("ex2.approx.f16x2 %0, %1;" : "=r"(r) : "r"(t));
    return r;
}

__device__ __forceinline__ void mma_f16(float c[4],
                                        uint32_t a0, uint32_t a1, uint32_t a2, uint32_t a3,
                                        uint32_t b0, uint32_t b1) {
    asm volatile(
        "mma.sync.aligned.m16n8k16.row.col.f32.f16.f16.f32 "
        "{%0,%1,%2,%3}, {%4,%5,%6,%7}, {%8,%9}, {%0,%1,%2,%3};\n"
        : "+f"(c[0]), "+f"(c[1]), "+f"(c[2]), "+f"(c[3])
        : "r"(a0), "r"(a1), "r"(a2), "r"(a3), "r"(b0), "r"(b1));
}

__device__ __forceinline__ void ldsm_x4(uint32_t d[4], uint32_t addr) {
    asm volatile("ldmatrix.sync.aligned.m8n8.x4.shared.b16 {%0,%1,%2,%3}, [%4];"
                 : "=r"(d[0]), "=r"(d[1]), "=r"(d[2]), "=r"(d[3]) : "r"(addr));
}
__device__ __forceinline__ void ldsm_x4t(uint32_t d[4], uint32_t addr) {
    asm volatile("ldmatrix.sync.aligned.m8n8.x4.trans.shared.b16 {%0,%1,%2,%3}, [%4];"
                 : "=r"(d[0]), "=r"(d[1]), "=r"(d[2]), "=r"(d[3]) : "r"(addr));
}

template<int N> __device__ __forceinline__ void cp_wait() {
    asm volatile("cp.async.wait_group %0;" :: "n"(N) : "memory");
}

#define L2E 1.4426950408889634f
#define ONE2 0x3C003C00u   // fp16 {1.0, 1.0}

// ---------------------------------------------------------------------------
// fp32 -> fp16 pair converter (grid-stride, float4 -> uint2)
// ---------------------------------------------------------------------------
__global__ void cvt_h_kernel(const float* __restrict__ x,
                             uint32_t* __restrict__ yh, int n4) {
    int i = blockIdx.x * blockDim.x + threadIdx.x;
    int stride = gridDim.x * blockDim.x;
    for (; i < n4; i += stride) {
        float4 v = ((const float4*)x)[i];
        ((uint2*)yh)[i] = make_uint2(f2h2(v.x, v.y), f2h2(v.z, v.w));
    }
}

// ---------------------------------------------------------------------------
// Mask packing: bit j of pm[i/32] = (mask[i] != 0). 1 warp handles 1024 ints.
// ---------------------------------------------------------------------------
__device__ __forceinline__ uint32_t spread4(uint32_t x) {
    x &= 0xFFu;
    x = (x | (x << 12)) & 0x000F000Fu;
    x = (x | (x << 6))  & 0x03030303u;
    x = (x | (x << 3))  & 0x11111111u;
    return x;
}

__global__ void pack_mask_kernel(const int* __restrict__ mask,
                                 uint32_t* __restrict__ pm) {
    int w    = (blockIdx.x * blockDim.x + threadIdx.x) >> 5;
    int lane = threadIdx.x & 31;
    size_t base = (size_t)w * 1024;
    #pragma unroll
    for (int it = 0; it < 8; it++) {
        int4 v = *(const int4*)(mask + base + it * 128 + lane * 4);
        uint32_t b0 = __ballot_sync(0xffffffffu, v.x != 0);
        uint32_t b1 = __ballot_sync(0xffffffffu, v.y != 0);
        uint32_t b2 = __ballot_sync(0xffffffffu, v.z != 0);
        uint32_t b3 = __ballot_sync(0xffffffffu, v.w != 0);
        if (lane < 4) {
            uint32_t word =  spread4(b0 >> (8 * lane))
                          | (spread4(b1 >> (8 * lane)) << 1)
                          | (spread4(b2 >> (8 * lane)) << 2)
                          | (spread4(b3 >> (8 * lane)) << 3);
            pm[base / 32 + it * 4 + lane] = word;
        }
    }
}

// ---------------------------------------------------------------------------
// LayerNorm: one WARP per row, shuffle-only reduction, emits fp16 pairs.
// ---------------------------------------------------------------------------
__global__ __launch_bounds__(256)
void ln_kernel(const float* __restrict__ x,
               const float* __restrict__ gamma,
               const float* __restrict__ beta,
               uint32_t* __restrict__ yh) {
    const int lane = threadIdx.x & 31;
    const int row  = blockIdx.x * 8 + (threadIdx.x >> 5);
    const float4* xr = (const float4*)(x + (size_t)row * D_MODEL);

    float4 v[4];
    float s = 0.0f, ss = 0.0f;
    #pragma unroll
    for (int i = 0; i < 4; i++) {
        v[i] = xr[lane + 32 * i];
        s  += v[i].x + v[i].y + v[i].z + v[i].w;
        ss += v[i].x*v[i].x + v[i].y*v[i].y + v[i].z*v[i].z + v[i].w*v[i].w;
    }
    #pragma unroll
    for (int o = 16; o > 0; o >>= 1) {
        s  += __shfl_xor_sync(0xffffffffu, s,  o);
        ss += __shfl_xor_sync(0xffffffffu, ss, o);
    }
    float mu  = s * (1.0f / D_MODEL);
    float var = ss * (1.0f / D_MODEL) - mu * mu;
    float rs  = rsqrtf(var + 1e-5f);

    uint2* yr = (uint2*)(yh + (size_t)row * (D_MODEL / 2));
    #pragma unroll
    for (int i = 0; i < 4; i++) {
        float4 g4 = ((const float4*)gamma)[lane + 32 * i];
        float4 b4 = ((const float4*)beta)[lane + 32 * i];
        float o0 = (v[i].x - mu) * rs * g4.x + b4.x;
        float o1 = (v[i].y - mu) * rs * g4.y + b4.y;
        float o2 = (v[i].z - mu) * rs * g4.z + b4.z;
        float o3 = (v[i].w - mu) * rs * g4.w + b4.w;
        yr[lane + 32 * i] = make_uint2(f2h2(o0, o1), f2h2(o2, o3));
    }
}

// ---------------------------------------------------------------------------
// Flash attention, fp16 mma + cp.async + ldmatrix.
// BM=128, 256 threads, warp tile 16x64.
// KV smem: ONE verbatim tile per stage [64 tok][72 fp16] (144B rows, pad 8).
//   - QK B-operand: ldmatrix.x4 (rows = keys)
//   - PV B-operand: ldmatrix.x4.trans (rows = k-dim)
// Q smem: [128][72 fp16] verbatim, pre-scaled by 1/8; frags via ldmatrix.x4.
// 3-stage cp.async ring, ONE barrier per tile.
// ---------------------------------------------------------------------------
#define BM    128
#define KVROW_B 144                      // bytes per KV/Q smem row (64 fp16 + pad 8)
#define KVSTG_B (64 * KVROW_B)           // 9216 B per stage
#define QSM_B   (128 * KVROW_B)          // 18432 B
#define ATTN_SMEM_BYTES (QSM_B + 3 * KVSTG_B)   // 46080 B
#define ROWU  (D_MODEL / 2)              // u32 per gmem row (256)

__global__ __launch_bounds__(256, 2)
void attn_mma_kernel(const uint32_t* __restrict__ Qh,
                     const uint32_t* __restrict__ KVh,
                     const uint32_t* __restrict__ pm,   // packed mask, may be null
                     const float* __restrict__ res,
                     float* __restrict__ out) {
    extern __shared__ uint8_t smraw[];
    uint8_t* Qsm  = smraw;
    uint8_t* KVsm = smraw + QSM_B;
    const uint32_t q_sa  = (uint32_t)__cvta_generic_to_shared(Qsm);
    const uint32_t kv_sa = (uint32_t)__cvta_generic_to_shared(KVsm);

    const int q0   = blockIdx.x * BM;
    const int h    = blockIdx.y;
    const int b    = blockIdx.z;
    const int tid  = threadIdx.x;
    const int lane = tid & 31;
    const int warp = tid >> 5;
    const int g    = lane >> 2;
    const int tig  = lane & 3;
    const int wrow = warp * 16;
    const int lm   = lane >> 3;          // ldmatrix matrix id 0..3
    const int lr   = lane & 7;           // ldmatrix row within matrix

    // ---- Stage Q [128 x 64] verbatim, scaled by 1/8 ----
    {
        const __half2 qscale = __float2half2_rn(0.125f);
        int r = tid >> 1, hh = tid & 1;
        const uint4* src = (const uint4*)(Qh + (size_t)(b * SEQ + q0 + r) * ROWU + h * 32 + hh * 16);
        uint4* dst = (uint4*)(Qsm + r * KVROW_B + hh * 64);
        #pragma unroll
        for (int c = 0; c < 4; c++) {
            uint4 u = src[c];
            uint32_t* uu = (uint32_t*)&u;
            #pragma unroll
            for (int k = 0; k < 4; k++) {
                __half2 hv = __hmul2(*(__half2*)&uu[k], qscale);
                uu[k] = *(uint32_t*)&hv;
            }
            dst[c] = u;
        }
    }

    float oacc[8][4];
    #pragma unroll
    for (int i = 0; i < 8; i++)
        #pragma unroll
        for (int j = 0; j < 4; j++) oacc[i][j] = 0.0f;
    float sumacc[4] = {0.0f, 0.0f, 0.0f, 0.0f};
    float mrow[2] = {-INFINITY, -INFINITY};

    // cp.async loader: 512 16B-chunks per tile, 2 per thread
    auto cp_tile = [&](int k0, int stg) {
        const uint32_t dbase = kv_sa + stg * KVSTG_B;
        #pragma unroll
        for (int i = 0; i < 2; i++) {
            int ci  = tid + i * 256;
            int row = ci >> 3, ch = ci & 7;
            const uint32_t* src = KVh + (size_t)(b * SEQ + k0 + row) * ROWU + h * 32 + ch * 4;
            uint32_t dst = dbase + row * KVROW_B + ch * 16;
            asm volatile("cp.async.cg.shared.global [%0], [%1], 16;"
                         :: "r"(dst), "l"(src) : "memory");
        }
        asm volatile("cp.async.commit_group;" ::: "memory");
    };

    const int NT = SEQ / 64;
    cp_tile(0, 0);

    int stage = 0;
    for (int kt = 0; kt < NT; kt++) {
        if (kt + 1 < NT) {
            cp_tile((kt + 1) * 64, (stage == 2) ? 0 : stage + 1);
            cp_wait<1>();
        } else {
            cp_wait<0>();
        }
        __syncthreads();   // stage ready; also orders Q staging (kt=0) and stage reuse
        const uint32_t kvb = kv_sa + stage * KVSTG_B;

        uint2 pmA, pmB;
        if (pm != nullptr) {
            const uint32_t* pr = pm + ((size_t)(b * SEQ + q0 + wrow + g)) * (SEQ / 32) + kt * 2;
            pmA = *(const uint2*)pr;
            pmB = *(const uint2*)(pr + (size_t)8 * (SEQ / 32));
        }

        // ---- S = Q K^T ----
        float sacc[8][4];
        #pragma unroll
        for (int i = 0; i < 8; i++)
            #pragma unroll
            for (int j = 0; j < 4; j++) sacc[i][j] = 0.0f;

        #pragma unroll
        for (int ksp = 0; ksp < 2; ksp++) {   // ks pairs (2ksp, 2ksp+1)
            uint32_t qf0[4], qf1[4];
            {
                uint32_t qa = q_sa + (wrow + (lm & 1) * 8 + lr) * KVROW_B
                                   + ksp * 64 + (lm >> 1) * 16;
                ldsm_x4(qf0, qa);          // ks = 2ksp   (cols +0/+16)
                ldsm_x4(qf1, qa + 32);     // ks = 2ksp+1 (cols +32/+48)
            }
            #pragma unroll
            for (int nf = 0; nf < 8; nf++) {
                uint32_t kb[4];
                ldsm_x4(kb, kvb + (8 * nf + lr) * KVROW_B + ksp * 64 + lm * 16);
                mma_f16(sacc[nf], qf0[0], qf0[1], qf0[2], qf0[3], kb[0], kb[1]);
                mma_f16(sacc[nf], qf1[0], qf1[1], qf1[2], qf1[3], kb[2], kb[3]);
            }
        }

        if (pm != nullptr) {
            #pragma unroll
            for (int nf = 0; nf < 8; nf++) {
                uint32_t wA = (nf < 4) ? pmA.x : pmA.y;
                uint32_t wB = (nf < 4) ? pmB.x : pmB.y;
                int sh = ((nf & 3) * 8) + 2 * tig;
                if (!((wA >> sh) & 1u)) sacc[nf][0] = -1e9f;
                if (!((wA >> sh) & 2u)) sacc[nf][1] = -1e9f;
                if (!((wB >> sh) & 1u)) sacc[nf][2] = -1e9f;
                if (!((wB >> sh) & 2u)) sacc[nf][3] = -1e9f;
            }
        }

        // ---- online softmax ----
        float tm0 = -INFINITY, tm1 = -INFINITY;
        #pragma unroll
        for (int nf = 0; nf < 8; nf++) {
            tm0 = fmaxf(tm0, fmaxf(sacc[nf][0], sacc[nf][1]));
            tm1 = fmaxf(tm1, fmaxf(sacc[nf][2], sacc[nf][3]));
        }
        tm0 = fmaxf(tm0, __shfl_xor_sync(0xffffffffu, tm0, 1));
        tm0 = fmaxf(tm0, __shfl_xor_sync(0xffffffffu, tm0, 2));
        tm1 = fmaxf(tm1, __shfl_xor_sync(0xffffffffu, tm1, 1));
        tm1 = fmaxf(tm1, __shfl_xor_sync(0xffffffffu, tm1, 2));

        float mn0 = fmaxf(mrow[0], tm0), mn1 = fmaxf(mrow[1], tm1);
        float c0 = __expf(mrow[0] - mn0), c1 = __expf(mrow[1] - mn1);
        mrow[0] = mn0; mrow[1] = mn1;
        float nb0 = -mn0 * L2E, nb1 = -mn1 * L2E;

        uint32_t pA[4][4];
        #pragma unroll
        for (int ks = 0; ks < 4; ks++) {
            int e = 2 * ks, o = 2 * ks + 1;
            pA[ks][0] = hex2(f2h2(fmaf(sacc[e][0], L2E, nb0), fmaf(sacc[e][1], L2E, nb0)));
            pA[ks][1] = hex2(f2h2(fmaf(sacc[e][2], L2E, nb1), fmaf(sacc[e][3], L2E, nb1)));
            pA[ks][2] = hex2(f2h2(fmaf(sacc[o][0], L2E, nb0), fmaf(sacc[o][1], L2E, nb0)));
            pA[ks][3] = hex2(f2h2(fmaf(sacc[o][2], L2E, nb1), fmaf(sacc[o][3], L2E, nb1)));
        }

        #pragma unroll
        for (int df = 0; df < 8; df++) {
            oacc[df][0] *= c0; oacc[df][1] *= c0;
            oacc[df][2] *= c1; oacc[df][3] *= c1;
        }
        sumacc[0] *= c0; sumacc[1] *= c0;
        sumacc[2] *= c1; sumacc[3] *= c1;

        // ---- O += P V  (V from the SAME KV tile, via trans ldmatrix) ----
        #pragma unroll
        for (int ks = 0; ks < 4; ks++) {
            mma_f16(sumacc, pA[ks][0], pA[ks][1], pA[ks][2], pA[ks][3], ONE2, ONE2);
            #pragma unroll
            for (int dfp = 0; dfp < 4; dfp++) {   // df pairs (2dfp, 2dfp+1)
                uint32_t vb[4];
                ldsm_x4t(vb, kvb + (16 * ks + (lm & 1) * 8 + lr) * KVROW_B
                                 + dfp * 32 + (lm >> 1) * 16);
                mma_f16(oacc[2*dfp],     pA[ks][0], pA[ks][1], pA[ks][2], pA[ks][3], vb[0], vb[1]);
                mma_f16(oacc[2*dfp + 1], pA[ks][0], pA[ks][1], pA[ks][2], pA[ks][3], vb[2], vb[3]);
            }
        }

        stage = (stage == 2) ? 0 : stage + 1;
    }

    // ---- epilogue: normalize + residual ----
    float inv0 = 1.0f / sumacc[0], inv1 = 1.0f / sumacc[2];
    int r = q0 + wrow + g;
    #pragma unroll
    for (int df = 0; df < 8; df++) {
        size_t idx0 = ((size_t)(b * SEQ + r)) * D_MODEL + h * DKH + df * 8 + 2 * tig;
        size_t idx1 = idx0 + (size_t)8 * D_MODEL;
        float2 ra = *(const float2*)(res + idx0);
        float2 rb = *(const float2*)(res + idx1);
        float2 oa, ob;
        oa.x = ra.x + oacc[df][0] * inv0;
        oa.y = ra.y + oacc[df][1] * inv0;
        ob.x = rb.x + oacc[df][2] * inv1;
        ob.y = rb.y + oacc[df][3] * inv1;
        *(float2*)(out + idx0) = oa;
        *(float2*)(out + idx1) = ob;
    }
}

// ---------------------------------------------------------------------------
// fp16 mma GEMM (exact R13-validated config): C = A @ B + bias (+ReLU),
// out fp32 or fp16. Block 128x128, BK=32, 256 threads, warp tile 16x128.
// Double-buffered static smem, ONE __syncthreads per k-step.
// ---------------------------------------------------------------------------
#define GA_S 12
#define GB_S 132
#define ASTG (128 * GA_S)
#define BSTG (8 * GB_S)

template<bool RELU, bool RES, bool HOUT>
__global__ __launch_bounds__(256, 2)
void gemm_mma(const uint32_t* __restrict__ A,   // fp16 pairs, [M][K/2]
              const uint32_t* __restrict__ B,   // fp16 pairs, [K][N/2]
              const float* __restrict__ bias,
              const float* __restrict__ res,
              void* __restrict__ Cv,
              int M, int N, int K) {
    __shared__ uint2 Apb[2 * ASTG];
    __shared__ uint2 Bpb[2 * BSTG];

    const int n0   = blockIdx.x * 128;
    const int m0   = blockIdx.y * 128;
    const int tid  = threadIdx.x;
    const int lane = tid & 31;
    const int warp = tid >> 5;
    const int g    = lane >> 2;
    const int tig  = lane & 3;
    const int wrow = warp * 16;
    const int KU   = K / 2, NU = N / 2;

    const int ar  = tid >> 1, ah = tid & 1;
    const int bcc = tid & 31;
    const int bks = (tid >> 7) & 1, btr = (tid >> 5) & 3;
    const int br0 = bks * 16 + 2 * btr;

    uint4 af[2];
    uint2 bf[4];

    auto ldg_tiles = [&](int k0) {
        const uint32_t* as_ = A + (size_t)(m0 + ar) * KU + k0 / 2 + ah * 8;
        af[0] = *(const uint4*)as_;
        af[1] = *(const uint4*)(as_ + 4);
        const uint32_t* bs_ = B + (size_t)(k0 + br0) * NU + n0 / 2 + bcc * 2;
        bf[0] = *(const uint2*)bs_;
        bf[1] = *(const uint2*)(bs_ + (size_t)1 * NU);
        bf[2] = *(const uint2*)(bs_ + (size_t)8 * NU);
        bf[3] = *(const uint2*)(bs_ + (size_t)9 * NU);
    };
    auto sts_tiles = [&](uint2* Ap, uint2* Bp) {
        uint4* da = (uint4*)(Ap + ar * GA_S + ah * 4);
        da[0] = make_uint4(af[0].x, af[1].x, af[0].y, af[1].y);
        da[1] = make_uint4(af[0].z, af[1].z, af[0].w, af[1].w);
        uint4* db = (uint4*)(Bp + (bks * 4 + btr) * GB_S + bcc * 4);
        db[0] = make_uint4(h2lo(bf[0].x, bf[1].x), h2lo(bf[2].x, bf[3].x),
                           h2hi(bf[0].x, bf[1].x), h2hi(bf[2].x, bf[3].x));
        db[1] = make_uint4(h2lo(bf[0].y, bf[1].y), h2lo(bf[2].y, bf[3].y),
                           h2hi(bf[0].y, bf[1].y), h2hi(bf[2].y, bf[3].y));
    };

    float acc[16][4];
    #pragma unroll
    for (int i = 0; i < 16; i++)
        #pragma unroll
        for (int j = 0; j < 4; j++) acc[i][j] = 0.0f;

    ldg_tiles(0);

    int it = 0;
    for (int k0 = 0; k0 < K; k0 += 32, it++) {
        uint2* Ap = Apb + (it & 1) * ASTG;
        uint2* Bp = Bpb + (it & 1) * BSTG;
        sts_tiles(Ap, Bp);
        __syncthreads();   // stage ready; prev compute on other buffer done
        if (k0 + 32 < K) ldg_tiles(k0 + 32);

        #pragma unroll
        for (int ks = 0; ks < 2; ks++) {
            uint2 aa = Ap[(wrow + g)     * GA_S + ks * 4 + tig];
            uint2 ab = Ap[(wrow + 8 + g) * GA_S + ks * 4 + tig];
            #pragma unroll
            for (int nf = 0; nf < 16; nf++) {
                uint2 bb = Bp[(ks * 4 + tig) * GB_S + nf * 8 + g];
                mma_f16(acc[nf], aa.x, ab.x, aa.y, ab.y, bb.x, bb.y);
            }
        }
    }

    const int row0 = m0 + wrow + g;
    #pragma unroll
    for (int nf = 0; nf < 16; nf++) {
        int col = n0 + nf * 8 + 2 * tig;
        float2 bi = *(const float2*)(bias + col);
        float2 va, vb;
        va.x = acc[nf][0] + bi.x; va.y = acc[nf][1] + bi.y;
        vb.x = acc[nf][2] + bi.x; vb.y = acc[nf][3] + bi.y;
        if (RELU) {
            va.x = fmaxf(va.x, 0.0f); va.y = fmaxf(va.y, 0.0f);
            vb.x = fmaxf(vb.x, 0.0f); vb.y = fmaxf(vb.y, 0.0f);
        }
        if (HOUT) {
            uint32_t* C = (uint32_t*)Cv;
            C[((size_t)row0 * N + col) / 2]       = f2h2(va.x, va.y);
            C[((size_t)(row0 + 8) * N + col) / 2] = f2h2(vb.x, vb.y);
        } else {
            float* C = (float*)Cv;
            size_t idx0 = (size_t)row0 * N + col;
            size_t idx1 = idx0 + (size_t)8 * N;
            if (RES) {
                float2 ra = *(const float2*)(res + idx0);
                float2 rb = *(const float2*)(res + idx1);
                va.x += ra.x; va.y += ra.y;
                vb.x += rb.x; vb.y += rb.y;
            }
            *(float2*)(C + idx0) = va;
            *(float2*)(C + idx1) = vb;
        }
    }
}

// ---------------------------------------------------------------------------
extern "C" void kernel_launch(void* const* d_in, const int* in_sizes, int n_in,
                              void* d_out, int out_size) {
    const float* x    = (const float*)d_in[0];
    const float* enc  = (const float*)d_in[1];
    const int*   mask = (const int*)  d_in[2];
    const float* ln1g = (const float*)d_in[3];
    const float* ln1b = (const float*)d_in[4];
    const float* ln2g = (const float*)d_in[5];
    const float* ln2b = (const float*)d_in[6];
    const float* ln3g = (const float*)d_in[7];
    const float* ln3b = (const float*)d_in[8];
    const float* W1   = (const float*)d_in[9];
    const float* b1   = (const float*)d_in[10];
    const float* W2   = (const float*)d_in[11];
    const float* b2   = (const float*)d_in[12];
    float* out = (float*)d_out;

    float *gx;
    uint32_t *gxnh, *gench, *ghh, *gw1h, *gw2h, *gpm;
    cudaGetSymbolAddress((void**)&gx,    g_x);
    cudaGetSymbolAddress((void**)&gxnh,  g_xnh);
    cudaGetSymbolAddress((void**)&gench, g_ench);
    cudaGetSymbolAddress((void**)&ghh,   g_hh);
    cudaGetSymbolAddress((void**)&gw1h,  g_w1h);
    cudaGetSymbolAddress((void**)&gw2h,  g_w2h);
    cudaGetSymbolAddress((void**)&gpm,   g_pm);

    cudaFuncSetAttribute(attn_mma_kernel,
                         cudaFuncAttributeMaxDynamicSharedMemorySize,
                         ATTN_SMEM_BYTES);

    dim3 attn_grid(SEQ / BM, HEADS, BATCH);

    // one-time conversions (per launch)
    pack_mask_kernel<<<(BATCH * SEQ * SEQ) / 1024 / 8, 256>>>(mask, gpm);
    cvt_h_kernel<<<4096, 256>>>(enc, gench, NROWS * D_MODEL / 4);
    cvt_h_kernel<<<512,  256>>>(W1,  gw1h,  D_MODEL * D_FF / 4);
    cvt_h_kernel<<<512,  256>>>(W2,  gw2h,  D_FF * D_MODEL / 4);

    // 1) x1 = LN1(x); x' = x + selfattn(x1, mask)
    ln_kernel<<<NROWS / 8, 256>>>(x, ln1g, ln1b, gxnh);
    attn_mma_kernel<<<attn_grid, 256, ATTN_SMEM_BYTES>>>(gxnh, gxnh, gpm, x, gx);

    // 2) x1 = LN2(x'); x'' = x' + crossattn(x1, enc)
    ln_kernel<<<NROWS / 8, 256>>>(gx, ln2g, ln2b, gxnh);
    attn_mma_kernel<<<attn_grid, 256, ATTN_SMEM_BYTES>>>(gxnh, gench, nullptr, gx, gx);

    // 3) x1 = LN3(x''); out = x'' + relu(x1 W1 + b1) W2 + b2
    ln_kernel<<<NROWS / 8, 256>>>(gx, ln3g, ln3b, gxnh);
    gemm_mma<true,  false, true ><<<dim3(D_FF / 128,    NROWS / 128), 256>>>(
        gxnh, gw1h, b1, nullptr, ghh, NROWS, D_FF, D_MODEL);
    gemm_mma<false, true,  false><<<dim3(D_MODEL / 128, NROWS / 128), 256>>>(
        ghh, gw2h, b2, gx, out, NROWS, D_MODEL, D_FF);
}